// round 3
// baseline (speedup 1.0000x reference)
#include <cuda_runtime.h>

// ---------------------------------------------------------------------------
// SSD post-process in 2 kernels:
//  K1 k_scan : conf scan (8x float4 batched loads) -> prefilter -> exact
//              softmax -> direct warp-aggregated candidate emit + 512-bin hist
//  K2 k_post : cutoff (1 warp, shfl) -> compact -> [last block] hybrid bitonic
//              sort + decode -> flag release -> [all 128 resident blocks] IoU
//              matrix -> [last block] greedy NMS -> output + state reset
// ---------------------------------------------------------------------------

#define N_MAX    (1u << 21)
#define NB       512                // histogram bins over score bits
#define BSHIFT   12                 // 4096-ulp bins
#define BASEBITS 0x3F666666u        // bits(0.9f)
#define KTOP     512
#define SELCAP   1024
#define PREF_T   2.19f              // conservative prefilter: ln(9)=2.1972

__device__ unsigned long long      g_cands[N_MAX];
__device__ __align__(16) int       g_hist[NB];
__device__ int                     g_cand_count;
__device__ int                     g_sel_count;
__device__ unsigned                g_tick2;
__device__ unsigned                g_tick3;
__device__ unsigned                g_flag;
__device__ unsigned long long      g_sel[SELCAP];
__device__ float4                  g_box[KTOP];
__device__ float                   g_area[KTOP];
__device__ float                   g_score[KTOP];
__device__ unsigned                g_mask32[KTOP * 16];

// ---------------------------------------------------------------------------
// K1: each thread handles 8 float4 (16 priors); loads batched for MLP.
// ---------------------------------------------------------------------------
__global__ void __launch_bounds__(256) k_scan(const float4* __restrict__ conf4, int n4) {
    int tid  = threadIdx.x;
    int lane = tid & 31;
    int base = blockIdx.x * 2048 + tid;

    float4 v[8];
#pragma unroll
    for (int k = 0; k < 8; ++k) {
        int i = base + k * 256;
        v[k] = (i < n4) ? __ldg(&conf4[i]) : make_float4(0.f, 0.f, 0.f, 0.f);
    }

    unsigned pm = 0;
#pragma unroll
    for (int k = 0; k < 8; ++k) {
        if (v[k].y - v[k].x > PREF_T) pm |= 1u << (2 * k);
        if (v[k].w - v[k].z > PREF_T) pm |= 1u << (2 * k + 1);
    }

    int cnt = __popc(pm);
    int pre = cnt;
#pragma unroll
    for (int s = 1; s < 32; s <<= 1) {
        int t = __shfl_up_sync(0xffffffffu, pre, s);
        if (lane >= s) pre += t;
    }
    int tot = __shfl_sync(0xffffffffu, pre, 31);
    if (tot) {
        int bs = 0;
        if (lane == 31) bs = atomicAdd(&g_cand_count, tot);
        bs = __shfl_sync(0xffffffffu, bs, 31);
        int w = bs + (pre - cnt);
#pragma unroll
        for (int k = 0; k < 8; ++k) {
#pragma unroll
            for (int e = 0; e < 2; ++e) {
                if (pm & (1u << (2 * k + e))) {
                    float c0 = e ? v[k].z : v[k].x;
                    float c1 = e ? v[k].w : v[k].y;
                    float s = 1.0f / (1.0f + expf(c0 - c1));   // exact softmax
                    unsigned long long key = 0ull;             // placeholder if s<=0.9
                    if (s > 0.9f) {
                        unsigned sb  = __float_as_uint(s);
                        unsigned idx = 2u * (unsigned)(base + k * 256) + (unsigned)e;
                        key = ((unsigned long long)sb << 32) |
                              (unsigned long long)(0xffffffffu - idx);
                        atomicAdd(&g_hist[(sb - BASEBITS) >> BSHIFT], 1);
                    }
                    g_cands[w++] = key;
                }
            }
        }
    }
}

// ---------------------------------------------------------------------------
// hybrid bitonic helpers (descending, 64-bit keys)
// ---------------------------------------------------------------------------
__device__ __forceinline__ unsigned long long bt_shfl(unsigned long long v, int j,
                                                      int k, int tid) {
    unsigned long long pv = __shfl_xor_sync(0xffffffffu, v, j);
    bool ilow   = (tid & j) == 0;
    bool maxlow = (tid & k) == 0;          // descending block: larger at lower idx
    bool keepmax = (ilow == maxlow);
    return keepmax ? (v > pv ? v : pv) : (v < pv ? v : pv);
}

// ---------------------------------------------------------------------------
// K2: grid MUST be <= 148 blocks (all resident) because of the spin-wait.
// ---------------------------------------------------------------------------
__global__ void __launch_bounds__(1024, 1) k_post(const float4* __restrict__ loc,
                                                  const float4* __restrict__ priors,
                                                  float* __restrict__ out) {
    __shared__ unsigned long long sbuf[SELCAP];   // 8KB (sort exchange)
    __shared__ unsigned um[KTOP * 16];            // 32KB (NMS matrix)
    __shared__ unsigned s_keepw[16];
    __shared__ int s_cut, s_last;
    int tid  = threadIdx.x;
    int lane = tid & 31;

    // ---- cutoff: single warp, shfl suffix scan over 512 bins ----
    if (tid == 0) s_cut = 0;
    if (tid < 32) {
        int cnt[16];
        int acc = 0;
#pragma unroll
        for (int q = 0; q < 4; ++q) {
            int4 h = ((const int4*)g_hist)[tid * 4 + q];
            cnt[q * 4 + 0] = h.x; cnt[q * 4 + 1] = h.y;
            cnt[q * 4 + 2] = h.z; cnt[q * 4 + 3] = h.w;
            acc += h.x + h.y + h.z + h.w;
        }
        int suf = acc;
#pragma unroll
        for (int s = 1; s < 32; s <<= 1) {
            int t = __shfl_down_sync(0xffffffffu, suf, s);
            if (lane + s < 32) suf += t;
        }
        int nsuf = __shfl_down_sync(0xffffffffu, suf, 1);
        if (lane == 31) nsuf = 0;
        if (suf >= KTOP && nsuf < KTOP) {
            int run = nsuf, cb = lane * 16;
#pragma unroll
            for (int r = 15; r >= 0; --r) {
                run += cnt[r];
                if (run >= KTOP) { cb = lane * 16 + r; break; }
            }
            s_cut = cb;
        }
    }
    __syncthreads();
    int cut = s_cut;

    // ---- compact: grid-stride over candidate buffer ----
    {
        int n = g_cand_count;
        if (n > (int)N_MAX) n = N_MAX;
        int total = gridDim.x * 1024;
        for (int i = blockIdx.x * 1024 + tid; i < n; i += total) {
            unsigned long long key = g_cands[i];
            unsigned sb = (unsigned)(key >> 32);
            if (sb > BASEBITS) {
                int bin = (int)((sb - BASEBITS) >> BSHIFT);
                if (bin >= cut) {
                    int p = atomicAdd(&g_sel_count, 1);
                    if (p < SELCAP) g_sel[p] = key;
                }
            }
        }
    }
    __threadfence();
    __syncthreads();
    if (tid == 0) s_last = (atomicAdd(&g_tick2, 1u) == gridDim.x - 1) ? 1 : 0;
    __syncthreads();

    if (s_last) {
        // ---- last block: hybrid bitonic sort (desc) + decode ----
        int ns = g_sel_count;
        if (ns > SELCAP) ns = SELCAP;
        unsigned long long v = (tid < ns) ? g_sel[tid] : 0ull;
#pragma unroll
        for (int k = 2; k <= 32; k <<= 1)
#pragma unroll
            for (int j = k >> 1; j >= 1; j >>= 1)
                v = bt_shfl(v, j, k, tid);
        for (int k = 64; k <= SELCAP; k <<= 1) {
            for (int j = k >> 1; j >= 32; j >>= 1) {
                sbuf[tid] = v;
                __syncthreads();
                unsigned long long pv = sbuf[tid ^ j];
                __syncthreads();
                bool ilow = (tid & j) == 0;
                bool maxlow = (tid & k) == 0;
                v = (ilow == maxlow) ? (v > pv ? v : pv) : (v < pv ? v : pv);
            }
#pragma unroll
            for (int j = 16; j >= 1; j >>= 1)
                v = bt_shfl(v, j, k, tid);
        }
        if (tid < KTOP) {
            unsigned long long key = v;
            float X1 = 0.f, Y1 = 0.f, X2 = 0.f, Y2 = 0.f, score = -1.0f;
            if (key != 0ull) {
                score = __uint_as_float((unsigned)(key >> 32));
                unsigned idx = 0xffffffffu - (unsigned)(key & 0xffffffffu);
                float4 l = __ldg(&loc[idx]);
                float4 p = __ldg(&priors[idx]);
                float cx = __fadd_rn(p.x, __fmul_rn(__fmul_rn(l.x, 0.1f), p.z));
                float cy = __fadd_rn(p.y, __fmul_rn(__fmul_rn(l.y, 0.1f), p.w));
                float w  = __fmul_rn(p.z, expf(__fmul_rn(l.z, 0.2f)));
                float h  = __fmul_rn(p.w, expf(__fmul_rn(l.w, 0.2f)));
                float x1 = __fsub_rn(cx, __fmul_rn(w, 0.5f));
                float y1 = __fsub_rn(cy, __fmul_rn(h, 0.5f));
                float x2 = __fadd_rn(x1, w);
                float y2 = __fadd_rn(y1, h);
                X1 = __fmul_rn(x1, 2048.0f);
                Y1 = __fmul_rn(y1, 2048.0f);
                X2 = __fmul_rn(x2, 2048.0f);
                Y2 = __fmul_rn(y2, 2048.0f);
            }
            g_box[tid]   = make_float4(X1, Y1, X2, Y2);
            g_area[tid]  = __fmul_rn(__fadd_rn(__fsub_rn(X2, X1), 1.0f),
                                     __fadd_rn(__fsub_rn(Y2, Y1), 1.0f));
            g_score[tid] = score;
        }
        __threadfence();
        __syncthreads();
        if (tid == 0) atomicExch(&g_flag, 1u);
    } else {
        if (tid == 0) {
            while (atomicAdd(&g_flag, 0u) == 0u) __nanosleep(64);
        }
        __syncthreads();
        __threadfence();
    }

    // ---- IoU matrix: threads tid<256 of each block, 8 columns each ----
    if (tid < 256) {
        int T  = blockIdx.x * 256 + tid;      // 0..32767
        int i  = T >> 6;
        int j0 = (T & 63) << 3;
        unsigned bits = 0u;
        float si = g_score[i];
        if (si > 0.0f) {
            float4 bi = g_box[i];
            float  ai = g_area[i];
#pragma unroll
            for (int b = 0; b < 8; ++b) {
                int j = j0 + b;
                float4 bj = g_box[j];
                float xx1 = fmaxf(bi.x, bj.x);
                float yy1 = fmaxf(bi.y, bj.y);
                float xx2 = fminf(bi.z, bj.z);
                float yy2 = fminf(bi.w, bj.w);
                float w = fmaxf(__fadd_rn(__fsub_rn(xx2, xx1), 1.0f), 0.0f);
                float h = fmaxf(__fadd_rn(__fsub_rn(yy2, yy1), 1.0f), 0.0f);
                float inter = __fmul_rn(w, h);
                float uni = __fsub_rn(__fadd_rn(ai, g_area[j]), inter);
                if (j > i && inter > __fmul_rn(0.4f, uni)) bits |= 1u << b;
            }
        }
        ((unsigned char*)g_mask32)[T] = (unsigned char)bits;
    }

    __threadfence();
    __syncthreads();
    if (tid == 0) s_last = (atomicAdd(&g_tick3, 1u) == gridDim.x - 1) ? 1 : 0;
    __syncthreads();
    if (!s_last) return;

    // ---- last block: serial greedy NMS + output + state reset ----
    for (int w = tid; w < KTOP * 16; w += 1024) um[w] = g_mask32[w];
    __syncthreads();

    if (tid < 32) {
        unsigned rem = 0u;                    // lanes 0..15 own column words
        for (int c = 0; c < 16; ++c) {
            unsigned val = __shfl_sync(0xffffffffu, rem, c);
            unsigned dm[32];
#pragma unroll
            for (int r = 0; r < 32; ++r) dm[r] = um[(c * 32 + r) * 16 + c];
#pragma unroll
            for (int r = 0; r < 32; ++r)
                if (!((val >> r) & 1u)) val |= dm[r];
            unsigned keep = ~val;
            if (tid < 16) {
#pragma unroll
                for (int r = 0; r < 32; ++r)
                    if ((keep >> r) & 1u) rem |= um[(c * 32 + r) * 16 + tid];
            }
        }
        if (tid < 16) s_keepw[tid] = rem;
    }
    __syncthreads();

    const float inv = 1.0f / 2048.0f;         // exact
    if (tid < KTOP) {
        int r = tid;
        float sc = g_score[r];
        bool kept = (sc > 0.0f) && !((s_keepw[r >> 5] >> (r & 31)) & 1u);
        float4 b = g_box[r];
        out[r * 5 + 0] = kept ? __fmul_rn(b.x, inv) : 0.0f;
        out[r * 5 + 1] = kept ? __fmul_rn(b.y, inv) : 0.0f;
        out[r * 5 + 2] = kept ? __fmul_rn(b.z, inv) : 0.0f;
        out[r * 5 + 3] = kept ? __fmul_rn(b.w, inv) : 0.0f;
        out[r * 5 + 4] = kept ? sc : 0.0f;
    }

    // tail reset for next graph replay (globals start zero-initialized)
    if (tid < NB) g_hist[tid] = 0;
    if (tid == 1024 - 1) {
        g_cand_count = 0;
        g_sel_count  = 0;
        g_tick2      = 0u;
        g_tick3      = 0u;
        g_flag       = 0u;
    }
}

// ---------------------------------------------------------------------------
extern "C" void kernel_launch(void* const* d_in, const int* in_sizes, int n_in,
                              void* d_out, int out_size) {
    const float4* loc    = (const float4*)d_in[0];   // [N,4]
    const float4* conf4  = (const float4*)d_in[1];   // [N,2] as float4 pairs
    const float4* priors = (const float4*)d_in[2];   // [N,4]
    float* out = (float*)d_out;                      // [512,5]
    int n  = in_sizes[0] / 4;
    int n4 = n >> 1;

    k_scan<<<(n4 + 2047) / 2048, 256>>>(conf4, n4);
    k_post<<<128, 1024>>>(loc, priors, out);
}